// round 5
// baseline (speedup 1.0000x reference)
#include <cuda_runtime.h>

#define LSEQ 512
#define NH   8
#define DH   64
#define MD   512

// ---------------- scratch (device globals; no allocation allowed) ----------
__device__ float g_q[LSEQ * MD];                 // [l, h*64+d], pre-scaled 1/8
__device__ float g_k[LSEQ * MD];                 // [m, h*64+d]
__device__ float g_v[LSEQ * MD];                 // [m, h*64+d]
__device__ float g_attn[NH * LSEQ * LSEQ];       // [h, l, m]
__device__ float g_ctx[LSEQ * MD];               // [l, h*64+d]

// ---------------- 64x64 GEMM tile core (vector LDS inner loop) -------------
__device__ __forceinline__ void gemm_tile_512(const float* __restrict__ A,
                                              const float* __restrict__ B,
                                              const float* __restrict__ bias,
                                              float* __restrict__ C,
                                              float scale) {
    __shared__ float As[16][64];
    __shared__ float Bs[16][68];
    const int tid = threadIdx.x;
    const int bm = blockIdx.y * 64;
    const int bn = blockIdx.x * 64;
    const int tr = (tid / 16) * 4;
    const int tc = (tid % 16) * 4;
    float acc[4][4] = {};

    const int am = tid >> 2;
    const int ak = (tid & 3) * 4;
    const int bk = tid >> 4;
    const int bn4 = (tid & 15) * 4;

    for (int k0 = 0; k0 < 512; k0 += 16) {
        float4 a = *(const float4*)(A + (bm + am) * 512 + k0 + ak);
        As[ak + 0][am] = a.x; As[ak + 1][am] = a.y;
        As[ak + 2][am] = a.z; As[ak + 3][am] = a.w;
        *(float4*)&Bs[bk][bn4] = *(const float4*)(B + (k0 + bk) * 512 + bn + bn4);
        __syncthreads();
#pragma unroll
        for (int kk = 0; kk < 16; kk++) {
            float4 ra = *(const float4*)&As[kk][tr];
            float4 rb = *(const float4*)&Bs[kk][tc];
            acc[0][0] += ra.x * rb.x; acc[0][1] += ra.x * rb.y;
            acc[0][2] += ra.x * rb.z; acc[0][3] += ra.x * rb.w;
            acc[1][0] += ra.y * rb.x; acc[1][1] += ra.y * rb.y;
            acc[1][2] += ra.y * rb.z; acc[1][3] += ra.y * rb.w;
            acc[2][0] += ra.z * rb.x; acc[2][1] += ra.z * rb.y;
            acc[2][2] += ra.z * rb.z; acc[2][3] += ra.z * rb.w;
            acc[3][0] += ra.w * rb.x; acc[3][1] += ra.w * rb.y;
            acc[3][2] += ra.w * rb.z; acc[3][3] += ra.w * rb.w;
        }
        __syncthreads();
    }
#pragma unroll
    for (int i = 0; i < 4; i++) {
        int row = bm + tr + i;
#pragma unroll
        for (int j = 0; j < 4; j++) {
            int col = bn + tc + j;
            C[row * 512 + col] = (acc[i][j] + bias[col]) * scale;
        }
    }
}

// ---------------- kernel 1: q/k/v projections ------------------------------
__global__ void __launch_bounds__(256) proj_kernel(
    const float* __restrict__ q_in, const float* __restrict__ k_in,
    const float* __restrict__ v_in,
    const float* __restrict__ Wq, const float* __restrict__ bq,
    const float* __restrict__ Wk, const float* __restrict__ bk,
    const float* __restrict__ Wv, const float* __restrict__ bv) {
    if (blockIdx.z == 0)      gemm_tile_512(q_in, Wq, bq, g_q, 0.125f);
    else if (blockIdx.z == 1) gemm_tile_512(k_in, Wk, bk, g_k, 1.0f);
    else                      gemm_tile_512(v_in, Wv, bv, g_v, 1.0f);
}

// ---------------- kernel 2: FUSED logits = q(k + rel_k)^T + softmax --------
// block handles (h, 4 consecutive l). k chunk staged in smem, reused x4 l.
// warp w: l = w>>1, m-half = (w&1)*64 within each 128-m chunk.
__global__ void __launch_bounds__(256) logits_softmax_fused(
    const float* __restrict__ rel_k, float* __restrict__ attn_out) {
    const int l0 = blockIdx.x * 4;
    const int h  = blockIdx.y;
    const int tid  = threadIdx.x;
    const int lane = tid & 31;
    const int warp = tid >> 5;
    const int li = lane & 15;     // d-quad index
    const int gg = lane >> 4;     // which of 2 m rows
    const int wl = warp >> 1;     // l (0..3)
    const int wm = (warp & 1) * 64;

    __shared__ float ks[128][72];
    __shared__ float s_logits[4][512];
    __shared__ float sq[4][64];
    __shared__ float s_red[8];
    __shared__ float s_red2[8];

    // stage q (4 rows x 64)
    if (tid < 64) {
        int l = tid >> 4, c4 = (tid & 15) * 4;
        *(float4*)&sq[l][c4] = *(const float4*)(g_q + (l0 + l) * 512 + h * 64 + c4);
    }
    __syncthreads();
    const float4 q4 = *(const float4*)&sq[wl][li * 4];

    const float* rkb = rel_k + ((size_t)(h * 512 + l0 + wl) * 512) * 64;
    const int sr = tid >> 4;          // staging row base
    const int sc4 = (tid & 15) * 4;   // staging col quad

    for (int mc = 0; mc < 4; mc++) {
        const int m0 = mc * 128;
        __syncthreads();   // ks reuse guard
#pragma unroll
        for (int j = 0; j < 8; j++)
            *(float4*)&ks[sr + j * 16][sc4] =
                *(const float4*)(g_k + (size_t)(m0 + sr + j * 16) * 512 + h * 64 + sc4);
        __syncthreads();

#pragma unroll 4
        for (int mi = 0; mi < 64; mi += 2) {
            const int mm = wm + mi + gg;          // m within chunk
            float4 r  = *(const float4*)(rkb + (size_t)(m0 + mm) * 64 + li * 4);
            float4 kk = *(const float4*)&ks[mm][li * 4];
            float s = q4.x * (r.x + kk.x) + q4.y * (r.y + kk.y)
                    + q4.z * (r.z + kk.z) + q4.w * (r.w + kk.w);
#pragma unroll
            for (int o = 8; o > 0; o >>= 1) s += __shfl_xor_sync(0xffffffffu, s, o);
            if (li == 0) s_logits[wl][m0 + mm] = s;
        }
    }
    __syncthreads();

    // ---- softmax: 64 threads per row (2 warps), 8 values per thread ----
    const int i  = tid & 63;
    const int sl = tid >> 6;
    float v[8];
#pragma unroll
    for (int j = 0; j < 8; j++) v[j] = s_logits[sl][i + j * 64];

    float mx = v[0];
#pragma unroll
    for (int j = 1; j < 8; j++) mx = fmaxf(mx, v[j]);
#pragma unroll
    for (int o = 16; o > 0; o >>= 1) mx = fmaxf(mx, __shfl_xor_sync(0xffffffffu, mx, o));
    if (lane == 0) s_red[warp] = mx;
    __syncthreads();
    const float bmx = fmaxf(s_red[2 * sl], s_red[2 * sl + 1]);

    float e[8];
    float sm = 0.f;
#pragma unroll
    for (int j = 0; j < 8; j++) { e[j] = __expf(v[j] - bmx); sm += e[j]; }
#pragma unroll
    for (int o = 16; o > 0; o >>= 1) sm += __shfl_xor_sync(0xffffffffu, sm, o);
    if (lane == 0) s_red2[warp] = sm;
    __syncthreads();
    const float inv = 1.0f / (s_red2[2 * sl] + s_red2[2 * sl + 1]);

    float* arow = g_attn + (size_t)(h * 512 + l0 + sl) * 512;
#pragma unroll
    for (int j = 0; j < 8; j++) arow[i + j * 64] = e[j] * inv;
    if (attn_out) {
        float* orow = attn_out + (size_t)(h * 512 + l0 + sl) * 512;
#pragma unroll
        for (int j = 0; j < 8; j++) orow[i + j * 64] = e[j] * inv;
    }
}

// ---------------- kernel 3: FUSED ctx = attn @ (v + rel_v) -----------------
// block (h, 4 l). v chunk staged in smem, reused x4 l. warp w owns
// (l = w>>1, d-half = (w&1)*32); lane owns one d. No atomics.
__global__ void __launch_bounds__(256) ctx_fused(const float* __restrict__ rel_v) {
    const int l0 = blockIdx.x * 4;
    const int h  = blockIdx.y;
    const int tid  = threadIdx.x;
    const int lane = tid & 31;
    const int warp = tid >> 5;
    const int wl = warp >> 1;
    const int d0 = (warp & 1) * 32;

    __shared__ float vs[128][72];
    __shared__ float s_a[4][512];

    // stage attn (4 contiguous rows = 2048 floats)
    {
        const float4* ga = (const float4*)(g_attn + (size_t)(h * 512 + l0) * 512);
        float4* sa = (float4*)&s_a[0][0];
        sa[tid] = ga[tid];
        sa[tid + 256] = ga[tid + 256];
    }

    const float* rvb = rel_v + ((size_t)(h * 512 + l0 + wl) * 512) * 64 + d0 + lane;
    const int sr = tid >> 4;
    const int sc4 = (tid & 15) * 4;

    float acc0 = 0.f, acc1 = 0.f;
    for (int mc = 0; mc < 4; mc++) {
        const int m0 = mc * 128;
        __syncthreads();
#pragma unroll
        for (int j = 0; j < 8; j++)
            *(float4*)&vs[sr + j * 16][sc4] =
                *(const float4*)(g_v + (size_t)(m0 + sr + j * 16) * 512 + h * 64 + sc4);
        __syncthreads();

#pragma unroll 4
        for (int m = 0; m < 128; m += 2) {
            float a0 = s_a[wl][m0 + m];
            float a1 = s_a[wl][m0 + m + 1];
            float rv0 = rvb[(size_t)(m0 + m) * 64];
            float rv1 = rvb[(size_t)(m0 + m + 1) * 64];
            float vv0 = vs[m][d0 + lane];
            float vv1 = vs[m + 1][d0 + lane];
            acc0 += a0 * (rv0 + vv0);
            acc1 += a1 * (rv1 + vv1);
        }
    }
    g_ctx[(l0 + wl) * 512 + h * 64 + d0 + lane] = acc0 + acc1;
}

// ---------------- kernel 4: out = bias-init then split-K GEMM --------------
__global__ void __launch_bounds__(256) out_init_kernel(
    const float* __restrict__ bo, float* __restrict__ out) {
    int idx = blockIdx.x * 256 + threadIdx.x;
    out[idx] = bo[idx & 511];
}

// grid (8 ntile, 8 mtile, 4 ksplit)
__global__ void __launch_bounds__(256) out_gemm_kernel(
    const float* __restrict__ Wo, float* __restrict__ out) {
    __shared__ float As[16][64];
    __shared__ float Bs[16][68];
    const int tid = threadIdx.x;
    const int bm = blockIdx.y * 64;
    const int bn = blockIdx.x * 64;
    const int kbase = blockIdx.z * 128;
    const int tr = (tid / 16) * 4;
    const int tc = (tid % 16) * 4;
    float acc[4][4] = {};

    const int am = tid >> 2;
    const int ak = (tid & 3) * 4;
    const int bk = tid >> 4;
    const int bn4 = (tid & 15) * 4;

    for (int k0 = kbase; k0 < kbase + 128; k0 += 16) {
        float4 a = *(const float4*)(g_ctx + (bm + am) * 512 + k0 + ak);
        As[ak + 0][am] = a.x; As[ak + 1][am] = a.y;
        As[ak + 2][am] = a.z; As[ak + 3][am] = a.w;
        *(float4*)&Bs[bk][bn4] = *(const float4*)(Wo + (k0 + bk) * 512 + bn + bn4);
        __syncthreads();
#pragma unroll
        for (int kk = 0; kk < 16; kk++) {
            float4 ra = *(const float4*)&As[kk][tr];
            float4 rb = *(const float4*)&Bs[kk][tc];
            acc[0][0] += ra.x * rb.x; acc[0][1] += ra.x * rb.y;
            acc[0][2] += ra.x * rb.z; acc[0][3] += ra.x * rb.w;
            acc[1][0] += ra.y * rb.x; acc[1][1] += ra.y * rb.y;
            acc[1][2] += ra.y * rb.z; acc[1][3] += ra.y * rb.w;
            acc[2][0] += ra.z * rb.x; acc[2][1] += ra.z * rb.y;
            acc[2][2] += ra.z * rb.z; acc[2][3] += ra.z * rb.w;
            acc[3][0] += ra.w * rb.x; acc[3][1] += ra.w * rb.y;
            acc[3][2] += ra.w * rb.z; acc[3][3] += ra.w * rb.w;
        }
        __syncthreads();
    }
#pragma unroll
    for (int i = 0; i < 4; i++)
#pragma unroll
        for (int j = 0; j < 4; j++)
            atomicAdd(&out[(bm + tr + i) * 512 + bn + tc + j], acc[i][j]);
}

// ---------------- launch ---------------------------------------------------
extern "C" void kernel_launch(void* const* d_in, const int* in_sizes, int n_in,
                              void* d_out, int out_size) {
    const float* query = (const float*)d_in[0];
    const float* key   = (const float*)d_in[1];
    const float* value = (const float*)d_in[2];
    const float* rel_k = (const float*)d_in[3];
    const float* rel_v = (const float*)d_in[4];
    const float* Wq = (const float*)d_in[5];
    const float* bq = (const float*)d_in[6];
    const float* Wk = (const float*)d_in[7];
    const float* bk = (const float*)d_in[8];
    const float* Wv = (const float*)d_in[9];
    const float* bv = (const float*)d_in[10];
    const float* Wo = (const float*)d_in[11];
    const float* bo = (const float*)d_in[12];

    float* out = (float*)d_out;
    float* attn_out = nullptr;
    const int OUT_ELEMS = 512 * 512;
    const int ATTN_ELEMS = 8 * 512 * 512;
    if (out_size >= OUT_ELEMS + ATTN_ELEMS) attn_out = out + OUT_ELEMS;

    out_init_kernel<<<OUT_ELEMS / 256, 256>>>(bo, out);

    dim3 proj_grid(8, 8, 3);
    proj_kernel<<<proj_grid, 256>>>(query, key, value, Wq, bq, Wk, bk, Wv, bv);

    dim3 fg(LSEQ / 4, NH);
    logits_softmax_fused<<<fg, 256>>>(rel_k, attn_out);
    ctx_fused<<<fg, 256>>>(rel_v);

    dim3 og(8, 8, 4);
    out_gemm_kernel<<<og, 256>>>(Wo, out);
}

// round 6
// speedup vs baseline: 1.1291x; 1.1291x over previous
#include <cuda_runtime.h>

#define LSEQ 512
#define NH   8
#define DH   64
#define MD   512

// ---------------- scratch (device globals; no allocation allowed) ----------
__device__ float g_q[LSEQ * MD];                 // [l, h*64+d], pre-scaled 1/8
__device__ float g_k[LSEQ * MD];                 // [m, h*64+d]
__device__ float g_v[LSEQ * MD];                 // [m, h*64+d]
__device__ float g_logits[NH * LSEQ * LSEQ];     // [h, l, m] : q k^T part
__device__ float g_attn[NH * LSEQ * LSEQ];       // [h, l, m]
__device__ float g_ctx[LSEQ * MD];               // [l, h*64+d]

// ---------------- kernel 0: seed accumulators with biases ------------------
__global__ void __launch_bounds__(256) init_kernel(
    const float* __restrict__ bq, const float* __restrict__ bk,
    const float* __restrict__ bv, const float* __restrict__ bo,
    float* __restrict__ out) {
    int idx = blockIdx.x * 256 + threadIdx.x;   // 0 .. 262143
    int c = idx & 511;
    g_q[idx] = bq[c] * 0.125f;
    g_k[idx] = bk[c];
    g_v[idx] = bv[c];
    out[idx] = bo[c];
}

// ---------------- shared 64x64 x 128k split tile body ----------------------
__device__ __forceinline__ void gemm_splitk_body(
    const float* __restrict__ A, const float* __restrict__ B,
    int bm, int bn, int kbase, float acc[4][4]) {
    __shared__ float As[16][64];
    __shared__ float Bs[16][68];
    const int tid = threadIdx.x;
    const int tr = (tid / 16) * 4;
    const int tc = (tid % 16) * 4;
    const int am = tid >> 2;
    const int ak = (tid & 3) * 4;
    const int bk = tid >> 4;
    const int bn4 = (tid & 15) * 4;

    for (int k0 = kbase; k0 < kbase + 128; k0 += 16) {
        float4 a = *(const float4*)(A + (bm + am) * 512 + k0 + ak);
        As[ak + 0][am] = a.x; As[ak + 1][am] = a.y;
        As[ak + 2][am] = a.z; As[ak + 3][am] = a.w;
        *(float4*)&Bs[bk][bn4] = *(const float4*)(B + (k0 + bk) * 512 + bn + bn4);
        __syncthreads();
#pragma unroll
        for (int kk = 0; kk < 16; kk++) {
            float4 ra = *(const float4*)&As[kk][tr];
            float4 rb = *(const float4*)&Bs[kk][tc];
            acc[0][0] += ra.x * rb.x; acc[0][1] += ra.x * rb.y;
            acc[0][2] += ra.x * rb.z; acc[0][3] += ra.x * rb.w;
            acc[1][0] += ra.y * rb.x; acc[1][1] += ra.y * rb.y;
            acc[1][2] += ra.y * rb.z; acc[1][3] += ra.y * rb.w;
            acc[2][0] += ra.z * rb.x; acc[2][1] += ra.z * rb.y;
            acc[2][2] += ra.z * rb.z; acc[2][3] += ra.z * rb.w;
            acc[3][0] += ra.w * rb.x; acc[3][1] += ra.w * rb.y;
            acc[3][2] += ra.w * rb.z; acc[3][3] += ra.w * rb.w;
        }
        __syncthreads();
    }
}

// ---------------- kernel 1: q/k/v projections, split-K=4 -------------------
// grid (8 ntile, 8 mtile, 12): z -> mat = z>>2, ksplit = z&3
__global__ void __launch_bounds__(256) proj_split_kernel(
    const float* __restrict__ q_in, const float* __restrict__ k_in,
    const float* __restrict__ v_in,
    const float* __restrict__ Wq, const float* __restrict__ Wk,
    const float* __restrict__ Wv) {
    const int mat = blockIdx.z >> 2;
    const int kbase = (blockIdx.z & 3) * 128;
    const int bm = blockIdx.y * 64;
    const int bn = blockIdx.x * 64;

    const float* A; const float* B; float* C; float scale;
    if (mat == 0)      { A = q_in; B = Wq; C = g_q; scale = 0.125f; }
    else if (mat == 1) { A = k_in; B = Wk; C = g_k; scale = 1.0f; }
    else               { A = v_in; B = Wv; C = g_v; scale = 1.0f; }

    float acc[4][4] = {};
    gemm_splitk_body(A, B, bm, bn, kbase, acc);

    const int tid = threadIdx.x;
    const int tr = (tid / 16) * 4;
    const int tc = (tid % 16) * 4;
#pragma unroll
    for (int i = 0; i < 4; i++)
#pragma unroll
        for (int j = 0; j < 4; j++)
            atomicAdd(&C[(bm + tr + i) * 512 + bn + tc + j], acc[i][j] * scale);
}

// ---------------- kernel 2: S = q @ k^T per head (K=64) --------------------
// grid (8 ntile, 8 mtile, 8 head)
__global__ void __launch_bounds__(256) qk_gemm_kernel() {
    __shared__ float As[16][64];
    __shared__ float Bs[16][68];
    const int tid = threadIdx.x;
    const int h = blockIdx.z;
    const int bm = blockIdx.y * 64;   // l tile
    const int bn = blockIdx.x * 64;   // m tile
    const int tr = (tid / 16) * 4;
    const int tc = (tid % 16) * 4;
    float acc[4][4] = {};

    const int r = tid >> 2;
    const int kq = (tid & 3) * 4;

    const float* Ah = g_q + h * 64;
    const float* Bh = g_k + h * 64;

    for (int k0 = 0; k0 < 64; k0 += 16) {
        float4 a = *(const float4*)(Ah + (bm + r) * 512 + k0 + kq);
        As[kq + 0][r] = a.x; As[kq + 1][r] = a.y;
        As[kq + 2][r] = a.z; As[kq + 3][r] = a.w;
        float4 b = *(const float4*)(Bh + (bn + r) * 512 + k0 + kq);
        Bs[kq + 0][r] = b.x; Bs[kq + 1][r] = b.y;
        Bs[kq + 2][r] = b.z; Bs[kq + 3][r] = b.w;
        __syncthreads();
#pragma unroll
        for (int kk = 0; kk < 16; kk++) {
            float4 ra = *(const float4*)&As[kk][tr];
            float4 rb = *(const float4*)&Bs[kk][tc];
            acc[0][0] += ra.x * rb.x; acc[0][1] += ra.x * rb.y;
            acc[0][2] += ra.x * rb.z; acc[0][3] += ra.x * rb.w;
            acc[1][0] += ra.y * rb.x; acc[1][1] += ra.y * rb.y;
            acc[1][2] += ra.y * rb.z; acc[1][3] += ra.y * rb.w;
            acc[2][0] += ra.z * rb.x; acc[2][1] += ra.z * rb.y;
            acc[2][2] += ra.z * rb.z; acc[2][3] += ra.z * rb.w;
            acc[3][0] += ra.w * rb.x; acc[3][1] += ra.w * rb.y;
            acc[3][2] += ra.w * rb.z; acc[3][3] += ra.w * rb.w;
        }
        __syncthreads();
    }
    float* Crow = g_logits + (size_t)(h * 512) * 512;
#pragma unroll
    for (int i = 0; i < 4; i++)
#pragma unroll
        for (int j = 0; j < 4; j++)
            Crow[(bm + tr + i) * 512 + bn + tc + j] = acc[i][j];
}

// ---------------- kernel 3: rel logits + softmax ---------------------------
// one block per (l, h); 256 threads = 8 warps; warp w handles m in [w*64, ...)
__global__ void __launch_bounds__(256) logits_softmax_kernel(
    const float* __restrict__ rel_k, float* __restrict__ attn_out) {
    const int l = blockIdx.x;
    const int h = blockIdx.y;
    const int tid = threadIdx.x;
    const int lane = tid & 31;
    const int warp = tid >> 5;
    const int li = lane & 15;
    const int gg = lane >> 4;

    __shared__ float s_logits[512];
    __shared__ float s_red[8];
    __shared__ float s_red2[8];

    const float4 q4 = *(const float4*)(g_q + l * 512 + h * 64 + li * 4);
    const float* rk_base = rel_k + ((size_t)(h * 512 + l) * 512) * 64;

    const int m_lo = warp * 64;
#pragma unroll 8
    for (int mi = 0; mi < 64; mi += 2) {
        const int m = m_lo + mi + gg;
        float4 r = *(const float4*)(rk_base + (size_t)m * 64 + li * 4);
        float s = q4.x * r.x + q4.y * r.y + q4.z * r.z + q4.w * r.w;
#pragma unroll
        for (int o = 8; o > 0; o >>= 1) s += __shfl_xor_sync(0xffffffffu, s, o);
        if (li == 0) s_logits[m] = s;
    }
    __syncthreads();

    const float* Srow = g_logits + (size_t)(h * 512 + l) * 512;
    float v0 = s_logits[tid] + Srow[tid];
    float v1 = s_logits[tid + 256] + Srow[tid + 256];
    float mx = fmaxf(v0, v1);
#pragma unroll
    for (int o = 16; o > 0; o >>= 1) mx = fmaxf(mx, __shfl_xor_sync(0xffffffffu, mx, o));
    if (lane == 0) s_red[warp] = mx;
    __syncthreads();
    float bmx = s_red[0];
#pragma unroll
    for (int i = 1; i < 8; i++) bmx = fmaxf(bmx, s_red[i]);

    float e0 = __expf(v0 - bmx);
    float e1 = __expf(v1 - bmx);
    float sm = e0 + e1;
#pragma unroll
    for (int o = 16; o > 0; o >>= 1) sm += __shfl_xor_sync(0xffffffffu, sm, o);
    if (lane == 0) s_red2[warp] = sm;
    __syncthreads();
    float bsum = s_red2[0];
#pragma unroll
    for (int i = 1; i < 8; i++) bsum += s_red2[i];
    const float inv = 1.0f / bsum;

    const float a0 = e0 * inv;
    const float a1 = e1 * inv;
    float* arow = g_attn + (size_t)(h * 512 + l) * 512;
    arow[tid] = a0;
    arow[tid + 256] = a1;
    if (attn_out) {
        float* orow = attn_out + (size_t)(h * 512 + l) * 512;
        orow[tid] = a0;
        orow[tid + 256] = a1;
    }
}

// ---------------- kernel 4: rel context base: g_ctx = attn ⊗ rel_v ---------
// one block per (l, h); 256 thr: 8 m-groups x 32 float2-d lanes
__global__ void __launch_bounds__(256) rctx_kernel(const float* __restrict__ rel_v) {
    const int l = blockIdx.x;
    const int h = blockIdx.y;
    const int tid = threadIdx.x;
    const int d2 = tid & 31;
    const int mg = tid >> 5;

    __shared__ float  s_a[512];
    __shared__ float2 s_p[256];

    const float* arow = g_attn + (size_t)(h * 512 + l) * 512;
    s_a[tid] = arow[tid];
    s_a[tid + 256] = arow[tid + 256];
    __syncthreads();

    const float2* rv = (const float2*)(rel_v + ((size_t)(h * 512 + l) * 512) * 64);

    float2 acc = make_float2(0.f, 0.f);
#pragma unroll 4
    for (int m = mg; m < 512; m += 16) {
        float a0 = s_a[m];
        float a1 = s_a[m + 8];
        float2 r0 = rv[(size_t)m * 32 + d2];
        float2 r1 = rv[(size_t)(m + 8) * 32 + d2];
        acc.x += a0 * r0.x + a1 * r1.x;
        acc.y += a0 * r0.y + a1 * r1.y;
    }
    s_p[tid] = acc;
    __syncthreads();
    if (tid < 32) {
        float2 r = s_p[tid];
#pragma unroll
        for (int g = 1; g < 8; g++) {
            float2 t = s_p[tid + g * 32];
            r.x += t.x; r.y += t.y;
        }
        *(float2*)(g_ctx + l * 512 + h * 64 + tid * 2) = r;
    }
}

// ---------------- kernel 5: g_ctx += attn @ v (split-K atomics) ------------
// grid (8 ltile, 4 ksplit, 8 head)
__global__ void __launch_bounds__(256) av_gemm_kernel() {
    __shared__ float As[16][64];
    __shared__ float Bs[16][68];
    const int tid = threadIdx.x;
    const int h = blockIdx.z;
    const int bm = blockIdx.x * 64;
    const int kbase = blockIdx.y * 128;
    const int tr = (tid / 16) * 4;
    const int tc = (tid % 16) * 4;
    float acc[4][4] = {};

    const int am = tid >> 2;
    const int ak = (tid & 3) * 4;
    const int bk = tid >> 4;
    const int bn4 = (tid & 15) * 4;

    const float* A = g_attn + (size_t)(h * 512) * 512;
    const float* B = g_v + h * 64;

    for (int k0 = kbase; k0 < kbase + 128; k0 += 16) {
        float4 a = *(const float4*)(A + (bm + am) * 512 + k0 + ak);
        As[ak + 0][am] = a.x; As[ak + 1][am] = a.y;
        As[ak + 2][am] = a.z; As[ak + 3][am] = a.w;
        *(float4*)&Bs[bk][bn4] = *(const float4*)(B + (k0 + bk) * 512 + bn4);
        __syncthreads();
#pragma unroll
        for (int kk = 0; kk < 16; kk++) {
            float4 ra = *(const float4*)&As[kk][tr];
            float4 rb = *(const float4*)&Bs[kk][tc];
            acc[0][0] += ra.x * rb.x; acc[0][1] += ra.x * rb.y;
            acc[0][2] += ra.x * rb.z; acc[0][3] += ra.x * rb.w;
            acc[1][0] += ra.y * rb.x; acc[1][1] += ra.y * rb.y;
            acc[1][2] += ra.y * rb.z; acc[1][3] += ra.y * rb.w;
            acc[2][0] += ra.z * rb.x; acc[2][1] += ra.z * rb.y;
            acc[2][2] += ra.z * rb.z; acc[2][3] += ra.z * rb.w;
            acc[3][0] += ra.w * rb.x; acc[3][1] += ra.w * rb.y;
            acc[3][2] += ra.w * rb.z; acc[3][3] += ra.w * rb.w;
        }
        __syncthreads();
    }
#pragma unroll
    for (int i = 0; i < 4; i++)
#pragma unroll
        for (int j = 0; j < 4; j++)
            atomicAdd(&g_ctx[(bm + tr + i) * 512 + h * 64 + tc + j], acc[i][j]);
}

// ---------------- kernel 6: out += ctx @ Wo (split-K atomics) --------------
// grid (8 ntile, 8 mtile, 4 ksplit)
__global__ void __launch_bounds__(256) out_gemm_kernel(
    const float* __restrict__ Wo, float* __restrict__ out) {
    const int bm = blockIdx.y * 64;
    const int bn = blockIdx.x * 64;
    const int kbase = blockIdx.z * 128;

    float acc[4][4] = {};
    gemm_splitk_body(g_ctx, Wo, bm, bn, kbase, acc);

    const int tid = threadIdx.x;
    const int tr = (tid / 16) * 4;
    const int tc = (tid % 16) * 4;
#pragma unroll
    for (int i = 0; i < 4; i++)
#pragma unroll
        for (int j = 0; j < 4; j++)
            atomicAdd(&out[(bm + tr + i) * 512 + bn + tc + j], acc[i][j]);
}

// ---------------- launch ---------------------------------------------------
extern "C" void kernel_launch(void* const* d_in, const int* in_sizes, int n_in,
                              void* d_out, int out_size) {
    const float* query = (const float*)d_in[0];
    const float* key   = (const float*)d_in[1];
    const float* value = (const float*)d_in[2];
    const float* rel_k = (const float*)d_in[3];
    const float* rel_v = (const float*)d_in[4];
    const float* Wq = (const float*)d_in[5];
    const float* bq = (const float*)d_in[6];
    const float* Wk = (const float*)d_in[7];
    const float* bk = (const float*)d_in[8];
    const float* Wv = (const float*)d_in[9];
    const float* bv = (const float*)d_in[10];
    const float* Wo = (const float*)d_in[11];
    const float* bo = (const float*)d_in[12];

    float* out = (float*)d_out;
    float* attn_out = nullptr;
    const int OUT_ELEMS = 512 * 512;
    const int ATTN_ELEMS = 8 * 512 * 512;
    if (out_size >= OUT_ELEMS + ATTN_ELEMS) attn_out = out + OUT_ELEMS;

    init_kernel<<<OUT_ELEMS / 256, 256>>>(bq, bk, bv, bo, out);

    dim3 pg(8, 8, 12);
    proj_split_kernel<<<pg, 256>>>(query, key, value, Wq, Wk, Wv);

    dim3 qkg(8, 8, 8);
    qk_gemm_kernel<<<qkg, 256>>>();

    dim3 lg(512, 8);
    logits_softmax_kernel<<<lg, 256>>>(rel_k, attn_out);
    rctx_kernel<<<lg, 256>>>(rel_v);

    dim3 avg(8, 4, 8);
    av_gemm_kernel<<<avg, 256>>>();

    dim3 og(8, 8, 4);
    out_gemm_kernel<<<og, 256>>>(Wo, out);
}

// round 7
// speedup vs baseline: 1.1478x; 1.0166x over previous
#include <cuda_runtime.h>

#define LSEQ 512
#define NH   8
#define DH   64
#define MD   512

typedef unsigned long long ull;

// ---------------- packed f32x2 helpers (sm_100+) ---------------------------
__device__ __forceinline__ ull pack2(float x, float y) {
    ull r; asm("mov.b64 %0, {%1, %2};" : "=l"(r) : "f"(x), "f"(y)); return r;
}
__device__ __forceinline__ void unpack2(ull v, float& x, float& y) {
    asm("mov.b64 {%0, %1}, %2;" : "=f"(x), "=f"(y) : "l"(v));
}
__device__ __forceinline__ void fma2(ull& d, ull a, ull b) {
    asm("fma.rn.f32x2 %0, %1, %2, %0;" : "+l"(d) : "l"(a), "l"(b));
}

// ---------------- scratch (device globals; no allocation allowed) ----------
__device__ float g_q[LSEQ * MD];                 // [l, h*64+d], pre-scaled 1/8
__device__ float g_k[LSEQ * MD];                 // [m, h*64+d]
__device__ float g_v[LSEQ * MD];                 // [m, h*64+d]
__device__ float g_logits[NH * LSEQ * LSEQ];     // [h, l, m] : q k^T part
__device__ float g_attn[NH * LSEQ * LSEQ];       // [h, l, m]
__device__ float g_ctx[LSEQ * MD];               // [l, h*64+d]

// ---------------- kernel 0: seed accumulators ------------------------------
__global__ void __launch_bounds__(256) init_kernel(
    const float* __restrict__ bq, const float* __restrict__ bk,
    const float* __restrict__ bv, const float* __restrict__ bo,
    float* __restrict__ out) {
    int idx = blockIdx.x * 256 + threadIdx.x;   // 0 .. 262143
    int c = idx & 511;
    g_q[idx] = bq[c] * 0.125f;
    g_k[idx] = bk[c];
    g_v[idx] = bv[c];
    g_ctx[idx] = 0.0f;
    out[idx] = bo[c];
}

// ---------------- 16-deep k-panel inner product, f32x2 packed --------------
// As[16][64] (k-major), Bs[16][68]; acc = 4 rows x 2 packed col-pairs
__device__ __forceinline__ void mma_panel_f32x2(
    const float (*As)[64], const float (*Bs)[68],
    int tr, int tc, ull acc[4][2]) {
#pragma unroll
    for (int kk = 0; kk < 16; kk++) {
        float4 ra = *(const float4*)&As[kk][tr];
        ull b01 = *(const ull*)&Bs[kk][tc];
        ull b23 = *(const ull*)&Bs[kk][tc + 2];
        ull a0 = pack2(ra.x, ra.x);
        ull a1 = pack2(ra.y, ra.y);
        ull a2 = pack2(ra.z, ra.z);
        ull a3 = pack2(ra.w, ra.w);
        fma2(acc[0][0], a0, b01); fma2(acc[0][1], a0, b23);
        fma2(acc[1][0], a1, b01); fma2(acc[1][1], a1, b23);
        fma2(acc[2][0], a2, b01); fma2(acc[2][1], a2, b23);
        fma2(acc[3][0], a3, b01); fma2(acc[3][1], a3, b23);
    }
}

// ---------------- shared 64x64 x 128k split tile body ----------------------
__device__ __forceinline__ void gemm_splitk_body(
    const float* __restrict__ A, const float* __restrict__ B,
    int bm, int bn, int kbase, ull acc[4][2]) {
    __shared__ float As[16][64];
    __shared__ float Bs[16][68];
    const int tid = threadIdx.x;
    const int tr = (tid / 16) * 4;
    const int tc = (tid % 16) * 4;
    const int am = tid >> 2;
    const int ak = (tid & 3) * 4;
    const int bk = tid >> 4;
    const int bn4 = (tid & 15) * 4;

    for (int k0 = kbase; k0 < kbase + 128; k0 += 16) {
        float4 a = *(const float4*)(A + (bm + am) * 512 + k0 + ak);
        As[ak + 0][am] = a.x; As[ak + 1][am] = a.y;
        As[ak + 2][am] = a.z; As[ak + 3][am] = a.w;
        *(float4*)&Bs[bk][bn4] = *(const float4*)(B + (k0 + bk) * 512 + bn + bn4);
        __syncthreads();
        mma_panel_f32x2(As, Bs, tr, tc, acc);
        __syncthreads();
    }
}

// ---------------- kernel 1: q/k/v projections, split-K=4 -------------------
// grid (8 ntile, 8 mtile, 12): z -> mat = z>>2, ksplit = z&3
__global__ void __launch_bounds__(256) proj_split_kernel(
    const float* __restrict__ q_in, const float* __restrict__ k_in,
    const float* __restrict__ v_in,
    const float* __restrict__ Wq, const float* __restrict__ Wk,
    const float* __restrict__ Wv) {
    const int mat = blockIdx.z >> 2;
    const int kbase = (blockIdx.z & 3) * 128;
    const int bm = blockIdx.y * 64;
    const int bn = blockIdx.x * 64;

    const float* A; const float* B; float* C; float scale;
    if (mat == 0)      { A = q_in; B = Wq; C = g_q; scale = 0.125f; }
    else if (mat == 1) { A = k_in; B = Wk; C = g_k; scale = 1.0f; }
    else               { A = v_in; B = Wv; C = g_v; scale = 1.0f; }

    ull acc[4][2] = {};
    gemm_splitk_body(A, B, bm, bn, kbase, acc);

    const int tid = threadIdx.x;
    const int tr = (tid / 16) * 4;
    const int tc = (tid % 16) * 4;
#pragma unroll
    for (int i = 0; i < 4; i++) {
        float c0, c1, c2, c3;
        unpack2(acc[i][0], c0, c1);
        unpack2(acc[i][1], c2, c3);
        float* row = C + (bm + tr + i) * 512 + bn + tc;
        atomicAdd(row + 0, c0 * scale);
        atomicAdd(row + 1, c1 * scale);
        atomicAdd(row + 2, c2 * scale);
        atomicAdd(row + 3, c3 * scale);
    }
}

// ---------------- kernel 2: S = q @ k^T per head (K=64) --------------------
// grid (8 ntile, 8 mtile, 8 head)
__global__ void __launch_bounds__(256) qk_gemm_kernel() {
    __shared__ float As[16][64];
    __shared__ float Bs[16][68];
    const int tid = threadIdx.x;
    const int h = blockIdx.z;
    const int bm = blockIdx.y * 64;   // l tile
    const int bn = blockIdx.x * 64;   // m tile
    const int tr = (tid / 16) * 4;
    const int tc = (tid % 16) * 4;
    ull acc[4][2] = {};

    const int r = tid >> 2;
    const int kq = (tid & 3) * 4;

    const float* Ah = g_q + h * 64;
    const float* Bh = g_k + h * 64;

    for (int k0 = 0; k0 < 64; k0 += 16) {
        float4 a = *(const float4*)(Ah + (bm + r) * 512 + k0 + kq);
        As[kq + 0][r] = a.x; As[kq + 1][r] = a.y;
        As[kq + 2][r] = a.z; As[kq + 3][r] = a.w;
        float4 b = *(const float4*)(Bh + (bn + r) * 512 + k0 + kq);
        Bs[kq + 0][r] = b.x; Bs[kq + 1][r] = b.y;
        Bs[kq + 2][r] = b.z; Bs[kq + 3][r] = b.w;
        __syncthreads();
        mma_panel_f32x2(As, Bs, tr, tc, acc);
        __syncthreads();
    }
    float* Crow = g_logits + (size_t)(h * 512) * 512;
#pragma unroll
    for (int i = 0; i < 4; i++) {
        float c0, c1, c2, c3;
        unpack2(acc[i][0], c0, c1);
        unpack2(acc[i][1], c2, c3);
        float* row = Crow + (bm + tr + i) * 512 + bn + tc;
        row[0] = c0; row[1] = c1; row[2] = c2; row[3] = c3;
    }
}

// ---------------- kernel 3: rel logits + softmax ---------------------------
// one block per (l, h); 256 threads = 8 warps; warp w handles m in [w*64, ...)
__global__ void __launch_bounds__(256) logits_softmax_kernel(
    const float* __restrict__ rel_k, float* __restrict__ attn_out) {
    const int l = blockIdx.x;
    const int h = blockIdx.y;
    const int tid = threadIdx.x;
    const int lane = tid & 31;
    const int warp = tid >> 5;
    const int li = lane & 15;
    const int gg = lane >> 4;

    __shared__ float s_logits[512];
    __shared__ float s_red[8];
    __shared__ float s_red2[8];

    const float4 q4 = *(const float4*)(g_q + l * 512 + h * 64 + li * 4);
    const float* rk_base = rel_k + ((size_t)(h * 512 + l) * 512) * 64;

    const int m_lo = warp * 64;
#pragma unroll 8
    for (int mi = 0; mi < 64; mi += 2) {
        const int m = m_lo + mi + gg;
        float4 r = *(const float4*)(rk_base + (size_t)m * 64 + li * 4);
        float s = q4.x * r.x + q4.y * r.y + q4.z * r.z + q4.w * r.w;
#pragma unroll
        for (int o = 8; o > 0; o >>= 1) s += __shfl_xor_sync(0xffffffffu, s, o);
        if (li == 0) s_logits[m] = s;
    }
    __syncthreads();

    const float* Srow = g_logits + (size_t)(h * 512 + l) * 512;
    float v0 = s_logits[tid] + Srow[tid];
    float v1 = s_logits[tid + 256] + Srow[tid + 256];
    float mx = fmaxf(v0, v1);
#pragma unroll
    for (int o = 16; o > 0; o >>= 1) mx = fmaxf(mx, __shfl_xor_sync(0xffffffffu, mx, o));
    if (lane == 0) s_red[warp] = mx;
    __syncthreads();
    float bmx = s_red[0];
#pragma unroll
    for (int i = 1; i < 8; i++) bmx = fmaxf(bmx, s_red[i]);

    float e0 = __expf(v0 - bmx);
    float e1 = __expf(v1 - bmx);
    float sm = e0 + e1;
#pragma unroll
    for (int o = 16; o > 0; o >>= 1) sm += __shfl_xor_sync(0xffffffffu, sm, o);
    if (lane == 0) s_red2[warp] = sm;
    __syncthreads();
    float bsum = s_red2[0];
#pragma unroll
    for (int i = 1; i < 8; i++) bsum += s_red2[i];
    const float inv = 1.0f / bsum;

    const float a0 = e0 * inv;
    const float a1 = e1 * inv;
    float* arow = g_attn + (size_t)(h * 512 + l) * 512;
    arow[tid] = a0;
    arow[tid + 256] = a1;
    if (attn_out) {
        float* orow = attn_out + (size_t)(h * 512 + l) * 512;
        orow[tid] = a0;
        orow[tid + 256] = a1;
    }
}

// ---------------- kernel 4: MERGED ctx accumulation ------------------------
// blocks [0, 4096): rctx stream  (l = bx & 511, h = bx >> 9)
// blocks [4096, 4352): av gemm   idx = bx-4096: bm=(idx&7)*64, ks=(idx>>3)&3, h=idx>>5
// both atomicAdd into zero-initialized g_ctx.
__global__ void __launch_bounds__(256) ctx_merged_kernel(const float* __restrict__ rel_v) {
    __shared__ float sbuf[16 * 64 + 16 * 68];   // 2112 floats, unioned usage
    const int tid = threadIdx.x;

    if (blockIdx.x < 4096) {
        // ---------------- rctx: g_ctx += attn . rel_v ----------------------
        const int l = blockIdx.x & 511;
        const int h = blockIdx.x >> 9;
        const int d2 = tid & 31;
        const int mg = tid >> 5;

        float*  s_a = sbuf;                       // [512]
        float2* s_p = (float2*)(sbuf + 512);      // [256]

        const float* arow = g_attn + (size_t)(h * 512 + l) * 512;
        s_a[tid] = arow[tid];
        s_a[tid + 256] = arow[tid + 256];
        __syncthreads();

        const float2* rv = (const float2*)(rel_v + ((size_t)(h * 512 + l) * 512) * 64);

        float2 acc = make_float2(0.f, 0.f);
#pragma unroll 4
        for (int m = mg; m < 512; m += 16) {
            float a0 = s_a[m];
            float a1 = s_a[m + 8];
            float2 r0 = rv[(size_t)m * 32 + d2];
            float2 r1 = rv[(size_t)(m + 8) * 32 + d2];
            acc.x += a0 * r0.x + a1 * r1.x;
            acc.y += a0 * r0.y + a1 * r1.y;
        }
        s_p[tid] = acc;
        __syncthreads();
        if (tid < 32) {
            float2 r = s_p[tid];
#pragma unroll
            for (int g = 1; g < 8; g++) {
                float2 t = s_p[tid + g * 32];
                r.x += t.x; r.y += t.y;
            }
            atomicAdd(&g_ctx[l * 512 + h * 64 + tid * 2 + 0], r.x);
            atomicAdd(&g_ctx[l * 512 + h * 64 + tid * 2 + 1], r.y);
        }
    } else {
        // ---------------- av: g_ctx += attn @ v (split-K) ------------------
        const int idx = blockIdx.x - 4096;
        const int bm = (idx & 7) * 64;
        const int kbase = ((idx >> 3) & 3) * 128;
        const int h = idx >> 5;

        float (*As)[64] = (float(*)[64])sbuf;
        float (*Bs)[68] = (float(*)[68])(sbuf + 16 * 64);

        const int tr = (tid / 16) * 4;
        const int tc = (tid % 16) * 4;
        const int am = tid >> 2;
        const int ak = (tid & 3) * 4;
        const int bk = tid >> 4;
        const int bn4 = (tid & 15) * 4;
        ull acc[4][2] = {};

        const float* A = g_attn + (size_t)(h * 512) * 512;
        const float* B = g_v + h * 64;

        for (int k0 = kbase; k0 < kbase + 128; k0 += 16) {
            float4 a = *(const float4*)(A + (bm + am) * 512 + k0 + ak);
            As[ak + 0][am] = a.x; As[ak + 1][am] = a.y;
            As[ak + 2][am] = a.z; As[ak + 3][am] = a.w;
            *(float4*)&Bs[bk][bn4] = *(const float4*)(B + (k0 + bk) * 512 + bn4);
            __syncthreads();
            mma_panel_f32x2(As, Bs, tr, tc, acc);
            __syncthreads();
        }
#pragma unroll
        for (int i = 0; i < 4; i++) {
            float c0, c1, c2, c3;
            unpack2(acc[i][0], c0, c1);
            unpack2(acc[i][1], c2, c3);
            float* row = g_ctx + (bm + tr + i) * 512 + h * 64 + tc;
            atomicAdd(row + 0, c0);
            atomicAdd(row + 1, c1);
            atomicAdd(row + 2, c2);
            atomicAdd(row + 3, c3);
        }
    }
}

// ---------------- kernel 5: out += ctx @ Wo (split-K atomics) --------------
// grid (8 ntile, 8 mtile, 4 ksplit)
__global__ void __launch_bounds__(256) out_gemm_kernel(
    const float* __restrict__ Wo, float* __restrict__ out) {
    const int bm = blockIdx.y * 64;
    const int bn = blockIdx.x * 64;
    const int kbase = blockIdx.z * 128;

    ull acc[4][2] = {};
    gemm_splitk_body(g_ctx, Wo, bm, bn, kbase, acc);

    const int tid = threadIdx.x;
    const int tr = (tid / 16) * 4;
    const int tc = (tid % 16) * 4;
#pragma unroll
    for (int i = 0; i < 4; i++) {
        float c0, c1, c2, c3;
        unpack2(acc[i][0], c0, c1);
        unpack2(acc[i][1], c2, c3);
        float* row = out + (bm + tr + i) * 512 + bn + tc;
        atomicAdd(row + 0, c0);
        atomicAdd(row + 1, c1);
        atomicAdd(row + 2, c2);
        atomicAdd(row + 3, c3);
    }
}

// ---------------- launch ---------------------------------------------------
extern "C" void kernel_launch(void* const* d_in, const int* in_sizes, int n_in,
                              void* d_out, int out_size) {
    const float* query = (const float*)d_in[0];
    const float* key   = (const float*)d_in[1];
    const float* value = (const float*)d_in[2];
    const float* rel_k = (const float*)d_in[3];
    const float* rel_v = (const float*)d_in[4];
    const float* Wq = (const float*)d_in[5];
    const float* bq = (const float*)d_in[6];
    const float* Wk = (const float*)d_in[7];
    const float* bk = (const float*)d_in[8];
    const float* Wv = (const float*)d_in[9];
    const float* bv = (const float*)d_in[10];
    const float* Wo = (const float*)d_in[11];
    const float* bo = (const float*)d_in[12];

    float* out = (float*)d_out;
    float* attn_out = nullptr;
    const int OUT_ELEMS = 512 * 512;
    const int ATTN_ELEMS = 8 * 512 * 512;
    if (out_size >= OUT_ELEMS + ATTN_ELEMS) attn_out = out + OUT_ELEMS;

    init_kernel<<<OUT_ELEMS / 256, 256>>>(bq, bk, bv, bo, out);

    dim3 pg(8, 8, 12);
    proj_split_kernel<<<pg, 256>>>(query, key, value, Wq, Wk, Wv);

    dim3 qkg(8, 8, 8);
    qk_gemm_kernel<<<qkg, 256>>>();

    dim3 lg(512, 8);
    logits_softmax_kernel<<<lg, 256>>>(rel_k, attn_out);

    ctx_merged_kernel<<<4096 + 256, 256>>>(rel_v);

    dim3 og(8, 8, 4);
    out_gemm_kernel<<<og, 256>>>(Wo, out);
}

// round 8
// speedup vs baseline: 1.2739x; 1.1099x over previous
#include <cuda_runtime.h>

#define LSEQ 512
#define NH   8
#define DH   64
#define MD   512

typedef unsigned long long ull;

// ---------------- packed f32x2 helpers (sm_100+) ---------------------------
__device__ __forceinline__ ull pack2(float x, float y) {
    ull r; asm("mov.b64 %0, {%1, %2};" : "=l"(r) : "f"(x), "f"(y)); return r;
}
__device__ __forceinline__ void unpack2(ull v, float& x, float& y) {
    asm("mov.b64 {%0, %1}, %2;" : "=f"(x), "=f"(y) : "l"(v));
}
__device__ __forceinline__ void fma2(ull& d, ull a, ull b) {
    asm("fma.rn.f32x2 %0, %1, %2, %0;" : "+l"(d) : "l"(a), "l"(b));
}

// ---------------- scratch (device globals; no allocation allowed) ----------
__device__ float g_q[LSEQ * MD];                 // [l, h*64+d], pre-scaled 1/8
__device__ float g_k[LSEQ * MD];                 // [m, h*64+d]
__device__ float g_v[LSEQ * MD];                 // [m, h*64+d]
__device__ float g_attn[NH * LSEQ * LSEQ];       // [h, l, m]
__device__ float g_ctx[LSEQ * MD];               // [l, h*64+d]

// ---------------- kernel 0: seed projection accumulators -------------------
__global__ void __launch_bounds__(256) init_kernel(
    const float* __restrict__ bq, const float* __restrict__ bk,
    const float* __restrict__ bv, const float* __restrict__ bo,
    float* __restrict__ out) {
    int idx = blockIdx.x * 256 + threadIdx.x;   // 0 .. 262143
    int c = idx & 511;
    g_q[idx] = bq[c] * 0.125f;
    g_k[idx] = bk[c];
    g_v[idx] = bv[c];
    out[idx] = bo[c];
}

// ---------------- 16-deep k-panel inner product, f32x2 packed --------------
__device__ __forceinline__ void mma_panel_f32x2(
    const float (*As)[64], const float (*Bs)[68],
    int tr, int tc, ull acc[4][2]) {
#pragma unroll
    for (int kk = 0; kk < 16; kk++) {
        float4 ra = *(const float4*)&As[kk][tr];
        ull b01 = *(const ull*)&Bs[kk][tc];
        ull b23 = *(const ull*)&Bs[kk][tc + 2];
        ull a0 = pack2(ra.x, ra.x);
        ull a1 = pack2(ra.y, ra.y);
        ull a2 = pack2(ra.z, ra.z);
        ull a3 = pack2(ra.w, ra.w);
        fma2(acc[0][0], a0, b01); fma2(acc[0][1], a0, b23);
        fma2(acc[1][0], a1, b01); fma2(acc[1][1], a1, b23);
        fma2(acc[2][0], a2, b01); fma2(acc[2][1], a2, b23);
        fma2(acc[3][0], a3, b01); fma2(acc[3][1], a3, b23);
    }
}

// ---------------- shared 64x64 x 128k split tile body ----------------------
__device__ __forceinline__ void gemm_splitk_body(
    const float* __restrict__ A, const float* __restrict__ B,
    int bm, int bn, int kbase, ull acc[4][2]) {
    __shared__ float As[16][64];
    __shared__ float Bs[16][68];
    const int tid = threadIdx.x;
    const int tr = (tid / 16) * 4;
    const int tc = (tid % 16) * 4;
    const int am = tid >> 2;
    const int ak = (tid & 3) * 4;
    const int bk = tid >> 4;
    const int bn4 = (tid & 15) * 4;

    for (int k0 = kbase; k0 < kbase + 128; k0 += 16) {
        float4 a = *(const float4*)(A + (bm + am) * 512 + k0 + ak);
        As[ak + 0][am] = a.x; As[ak + 1][am] = a.y;
        As[ak + 2][am] = a.z; As[ak + 3][am] = a.w;
        *(float4*)&Bs[bk][bn4] = *(const float4*)(B + (k0 + bk) * 512 + bn + bn4);
        __syncthreads();
        mma_panel_f32x2(As, Bs, tr, tc, acc);
        __syncthreads();
    }
}

// ---------------- kernel 1: q/k/v projections, split-K=4 -------------------
// grid (8 ntile, 8 mtile, 12): z -> mat = z>>2, ksplit = z&3
__global__ void __launch_bounds__(256) proj_split_kernel(
    const float* __restrict__ q_in, const float* __restrict__ k_in,
    const float* __restrict__ v_in,
    const float* __restrict__ Wq, const float* __restrict__ Wk,
    const float* __restrict__ Wv) {
    const int mat = blockIdx.z >> 2;
    const int kbase = (blockIdx.z & 3) * 128;
    const int bm = blockIdx.y * 64;
    const int bn = blockIdx.x * 64;

    const float* A; const float* B; float* C; float scale;
    if (mat == 0)      { A = q_in; B = Wq; C = g_q; scale = 0.125f; }
    else if (mat == 1) { A = k_in; B = Wk; C = g_k; scale = 1.0f; }
    else               { A = v_in; B = Wv; C = g_v; scale = 1.0f; }

    ull acc[4][2] = {};
    gemm_splitk_body(A, B, bm, bn, kbase, acc);

    const int tid = threadIdx.x;
    const int tr = (tid / 16) * 4;
    const int tc = (tid % 16) * 4;
#pragma unroll
    for (int i = 0; i < 4; i++) {
        float c0, c1, c2, c3;
        unpack2(acc[i][0], c0, c1);
        unpack2(acc[i][1], c2, c3);
        float* row = C + (bm + tr + i) * 512 + bn + tc;
        atomicAdd(row + 0, c0 * scale);
        atomicAdd(row + 1, c1 * scale);
        atomicAdd(row + 2, c2 * scale);
        atomicAdd(row + 3, c3 * scale);
    }
}

// ---------------- kernel 2: FUSED logits = q.(k + rel_k) + softmax ---------
// one block per (l, h); 256 threads = 8 warps; warp w handles m in [w*64, ...)
// k read inline from L2 (h-slice is L2-resident) — proven round-2 pattern.
__global__ void __launch_bounds__(256) logits_softmax_kernel(
    const float* __restrict__ rel_k, float* __restrict__ attn_out) {
    const int l = blockIdx.x;
    const int h = blockIdx.y;
    const int tid = threadIdx.x;
    const int lane = tid & 31;
    const int warp = tid >> 5;
    const int li = lane & 15;
    const int gg = lane >> 4;

    __shared__ float s_logits[512];
    __shared__ float s_red[8];
    __shared__ float s_red2[8];

    const float4 q4 = *(const float4*)(g_q + l * 512 + h * 64 + li * 4);
    const float* rk_base = rel_k + ((size_t)(h * 512 + l) * 512) * 64;
    const float* k_base = g_k + h * 64;

    const int m_lo = warp * 64;
#pragma unroll 8
    for (int mi = 0; mi < 64; mi += 2) {
        const int m = m_lo + mi + gg;
        float4 r  = *(const float4*)(rk_base + (size_t)m * 64 + li * 4);
        float4 kk = *(const float4*)(k_base + (size_t)m * 512 + li * 4);
        float s = q4.x * (r.x + kk.x) + q4.y * (r.y + kk.y)
                + q4.z * (r.z + kk.z) + q4.w * (r.w + kk.w);
#pragma unroll
        for (int o = 8; o > 0; o >>= 1) s += __shfl_xor_sync(0xffffffffu, s, o);
        if (li == 0) s_logits[m] = s;
    }
    __syncthreads();

    float v0 = s_logits[tid];
    float v1 = s_logits[tid + 256];
    float mx = fmaxf(v0, v1);
#pragma unroll
    for (int o = 16; o > 0; o >>= 1) mx = fmaxf(mx, __shfl_xor_sync(0xffffffffu, mx, o));
    if (lane == 0) s_red[warp] = mx;
    __syncthreads();
    float bmx = s_red[0];
#pragma unroll
    for (int i = 1; i < 8; i++) bmx = fmaxf(bmx, s_red[i]);

    float e0 = __expf(v0 - bmx);
    float e1 = __expf(v1 - bmx);
    float sm = e0 + e1;
#pragma unroll
    for (int o = 16; o > 0; o >>= 1) sm += __shfl_xor_sync(0xffffffffu, sm, o);
    if (lane == 0) s_red2[warp] = sm;
    __syncthreads();
    float bsum = s_red2[0];
#pragma unroll
    for (int i = 1; i < 8; i++) bsum += s_red2[i];
    const float inv = 1.0f / bsum;

    const float a0 = e0 * inv;
    const float a1 = e1 * inv;
    float* arow = g_attn + (size_t)(h * 512 + l) * 512;
    arow[tid] = a0;
    arow[tid + 256] = a1;
    if (attn_out) {
        float* orow = attn_out + (size_t)(h * 512 + l) * 512;
        orow[tid] = a0;
        orow[tid + 256] = a1;
    }
}

// ---------------- kernel 3: FUSED ctx = attn @ (v + rel_v) -----------------
// one block per (l, h); thread = (m-group 0..7, float2-d 0..31).
// v read inline from L2 (h-slice L2-resident). Single writer -> plain store.
__global__ void __launch_bounds__(256) ctx_kernel(const float* __restrict__ rel_v) {
    const int l = blockIdx.x;
    const int h = blockIdx.y;
    const int tid = threadIdx.x;
    const int d2 = tid & 31;
    const int mg = tid >> 5;

    __shared__ float  s_a[512];
    __shared__ float2 s_p[256];

    const float* arow = g_attn + (size_t)(h * 512 + l) * 512;
    s_a[tid] = arow[tid];
    s_a[tid + 256] = arow[tid + 256];
    __syncthreads();

    const float2* rv = (const float2*)(rel_v + ((size_t)(h * 512 + l) * 512) * 64);
    const float2* vv = (const float2*)(g_v + h * 64);   // row stride 256 float2

    float2 acc = make_float2(0.f, 0.f);
#pragma unroll 4
    for (int m = mg; m < 512; m += 16) {
        float a0 = s_a[m];
        float a1 = s_a[m + 8];
        float2 r0 = rv[(size_t)m * 32 + d2];
        float2 r1 = rv[(size_t)(m + 8) * 32 + d2];
        float2 v0 = vv[(size_t)m * 256 + d2];
        float2 v1 = vv[(size_t)(m + 8) * 256 + d2];
        acc.x += a0 * (r0.x + v0.x) + a1 * (r1.x + v1.x);
        acc.y += a0 * (r0.y + v0.y) + a1 * (r1.y + v1.y);
    }
    s_p[tid] = acc;
    __syncthreads();
    if (tid < 32) {
        float2 r = s_p[tid];
#pragma unroll
        for (int g = 1; g < 8; g++) {
            float2 t = s_p[tid + g * 32];
            r.x += t.x; r.y += t.y;
        }
        *(float2*)(g_ctx + l * 512 + h * 64 + tid * 2) = r;
    }
}

// ---------------- kernel 4: out += ctx @ Wo (split-K atomics) --------------
// grid (8 ntile, 8 mtile, 4 ksplit)
__global__ void __launch_bounds__(256) out_gemm_kernel(
    const float* __restrict__ Wo, float* __restrict__ out) {
    const int bm = blockIdx.y * 64;
    const int bn = blockIdx.x * 64;
    const int kbase = blockIdx.z * 128;

    ull acc[4][2] = {};
    gemm_splitk_body(g_ctx, Wo, bm, bn, kbase, acc);

    const int tid = threadIdx.x;
    const int tr = (tid / 16) * 4;
    const int tc = (tid % 16) * 4;
#pragma unroll
    for (int i = 0; i < 4; i++) {
        float c0, c1, c2, c3;
        unpack2(acc[i][0], c0, c1);
        unpack2(acc[i][1], c2, c3);
        float* row = out + (bm + tr + i) * 512 + bn + tc;
        atomicAdd(row + 0, c0);
        atomicAdd(row + 1, c1);
        atomicAdd(row + 2, c2);
        atomicAdd(row + 3, c3);
    }
}

// ---------------- launch ---------------------------------------------------
extern "C" void kernel_launch(void* const* d_in, const int* in_sizes, int n_in,
                              void* d_out, int out_size) {
    const float* query = (const float*)d_in[0];
    const float* key   = (const float*)d_in[1];
    const float* value = (const float*)d_in[2];
    const float* rel_k = (const float*)d_in[3];
    const float* rel_v = (const float*)d_in[4];
    const float* Wq = (const float*)d_in[5];
    const float* bq = (const float*)d_in[6];
    const float* Wk = (const float*)d_in[7];
    const float* bk = (const float*)d_in[8];
    const float* Wv = (const float*)d_in[9];
    const float* bv = (const float*)d_in[10];
    const float* Wo = (const float*)d_in[11];
    const float* bo = (const float*)d_in[12];

    float* out = (float*)d_out;
    float* attn_out = nullptr;
    const int OUT_ELEMS = 512 * 512;
    const int ATTN_ELEMS = 8 * 512 * 512;
    if (out_size >= OUT_ELEMS + ATTN_ELEMS) attn_out = out + OUT_ELEMS;

    init_kernel<<<OUT_ELEMS / 256, 256>>>(bq, bk, bv, bo, out);

    dim3 pg(8, 8, 12);
    proj_split_kernel<<<pg, 256>>>(query, key, value, Wq, Wk, Wv);

    dim3 lg(512, 8);
    logits_softmax_kernel<<<lg, 256>>>(rel_k, attn_out);
    ctx_kernel<<<lg, 256>>>(rel_v);

    dim3 og(8, 8, 4);
    out_gemm_kernel<<<og, 256>>>(Wo, out);
}